// round 15
// baseline (speedup 1.0000x reference)
#include <cuda_runtime.h>
#include <cstdint>

#define B_      64
#define P_      576
#define D_      768
#define G_      64
#define NN      65
#define SZ      4225      // 65*65
#define LDA     67        // odd: conflict-free column walks
#define STEPS_  8
#define FLOOR_  0.0001f
#define EPS_    0.0001f
#define DT_     0.1f
#define GAMMA_  0.1f

#define MPAD    4224      // 66*64, padded row count for GEMM tiles
#define ITPB    512       // k_iter threads per block (16 warps)
#define PBMAX   16        // elimination panel size

// Output layout offsets (flattened tuple, float32)
#define O_KEEP   0          // (64,577)
#define O_PATCH  36928      // (64,576)
#define O_GID    73792      // (64,576)
#define O_GS     110656     // (64,576)
#define O_DH     147520     // (64,9,65,65)
#define O_QH     2581120    // (64,8,65,65)
#define O_RT     4744320    // (64,64,64)
#define O_AUX    5006464    // 2 scalars

// Scratch (static device globals — zero-initialized at load, never alloc'd)
__device__ float g_nodes[MPAD*D_];      // padded rows 4160..4223 stay zero
__device__ float g_proj [MPAD*D_];
__device__ float g_gf   [B_*G_];
__device__ float g_aux  [B_*2];
__device__ float g_gpart[6*B_*SZ];      // split-K gram partials (raw dot products)

// Packed dual-fp32 FMA (FFMA2) — exact fp32, 2x FFMA throughput
#define FMA2(c, a, b) asm("fma.rn.f32x2 %0, %1, %2, %0;" : "+l"(c) : "l"(a), "l"(b))
// Duplicate one fp32 into both halves of a b64 (register-side, ALU pipe)
#define PACK2(d, s)   asm("mov.b64 %0, {%1, %1};" : "=l"(d) : "f"(s))

// ---------------------------------------------------------------------------
// Kernel A: group means + cls + keep-col init.  grid=(65,64), 192 threads
// ---------------------------------------------------------------------------
__global__ void k_group(const float* __restrict__ tokens,
                        const float* __restrict__ cls,
                        float* __restrict__ out) {
    int n = blockIdx.x;      // node 0..64
    int b = blockIdx.y;
    int tid = threadIdx.x;   // 0..191, one float4 each
    float4* dst = (float4*)(g_nodes + ((size_t)b*NN + n)*D_);
    if (n == 0) {
        dst[tid] = ((const float4*)(cls + (size_t)b*D_))[tid];
        if (tid == 0) out[O_KEEP + (size_t)b*577] = 1.0f;
    } else {
        int g  = n - 1;
        int r0 = (g >> 3) * 3, c0 = (g & 7) * 3;
        const float4* base = (const float4*)(tokens + (size_t)b*P_*D_);
        float4 s = make_float4(0.f, 0.f, 0.f, 0.f);
        #pragma unroll
        for (int dr = 0; dr < 3; dr++)
            #pragma unroll
            for (int dc = 0; dc < 3; dc++) {
                float4 v = base[(size_t)((r0+dr)*24 + (c0+dc))*(D_/4) + tid];
                s.x += v.x; s.y += v.y; s.z += v.z; s.w += v.w;
            }
        const float inv9 = 1.0f/9.0f;
        s.x *= inv9; s.y *= inv9; s.z *= inv9; s.w *= inv9;
        dst[tid] = s;
    }
}

// ---------------------------------------------------------------------------
// Kernel B: GEMM  proj[r,e] = sum_d nodes[r,d] * W[e,d]   (FFMA2, R4 version)
//   Tile 64x128x16, 128 threads, 16x4 microtile.  grid=(66,6)
// ---------------------------------------------------------------------------
__global__ void __launch_bounds__(128, 3) k_gemm(const float* __restrict__ Wm) {
    __shared__ float As[64][20];     // [m][k], pad 20
    __shared__ float Bs[16][132];    // [k][n], pad 132
    int tid  = threadIdx.x;
    int lane = tid & 31, w = tid >> 5;         // 4 warps
    int m0 = blockIdx.x * 64, n0 = blockIdx.y * 128;

    unsigned long long acc[16][2] = {};        // 16 m-rows x (2 f32x2 = 4 n)

    for (int k0 = 0; k0 < D_; k0 += 16) {
        #pragma unroll
        for (int h = 0; h < 2; h++) {
            int idx = tid + h*128;
            int row = idx >> 2, c4 = (idx & 3) << 2;
            float4 v = *(const float4*)(g_nodes + (size_t)(m0+row)*D_ + k0 + c4);
            *(float4*)&As[row][c4] = v;
        }
        #pragma unroll
        for (int h = 0; h < 4; h++) {
            int idx = tid + h*128;
            int row = idx >> 2, c4 = (idx & 3) << 2;
            float4 v = *(const float4*)(Wm + (size_t)(n0+row)*D_ + k0 + c4);
            Bs[c4+0][row] = v.x; Bs[c4+1][row] = v.y;
            Bs[c4+2][row] = v.z; Bs[c4+3][row] = v.w;
        }
        __syncthreads();
        #pragma unroll
        for (int kk2 = 0; kk2 < 8; kk2++) {
            float2 av[16];
            #pragma unroll
            for (int r = 0; r < 16; r++)
                av[r] = *(const float2*)&As[w*16 + r][kk2*2];   // broadcast
            #pragma unroll
            for (int e = 0; e < 2; e++) {
                int kk = kk2*2 + e;
                ulonglong2 bb = *(const ulonglong2*)&Bs[kk][lane*4];
                #pragma unroll
                for (int r = 0; r < 16; r++) {
                    unsigned long long a2;
                    PACK2(a2, e ? av[r].y : av[r].x);
                    FMA2(acc[r][0], a2, bb.x);
                    FMA2(acc[r][1], a2, bb.y);
                }
            }
        }
        __syncthreads();
    }
    #pragma unroll
    for (int r = 0; r < 16; r++) {
        float4 o;
        o.x = __uint_as_float((unsigned)(acc[r][0]));
        o.y = __uint_as_float((unsigned)(acc[r][0] >> 32));
        o.z = __uint_as_float((unsigned)(acc[r][1]));
        o.w = __uint_as_float((unsigned)(acc[r][1] >> 32));
        *(float4*)(g_proj + (size_t)(m0 + w*16 + r)*D_ + n0 + lane*4) = o;
    }
}

// ---------------------------------------------------------------------------
// Kernel C: per-batch Gram partials on RAW proj, split-K 6 x 128.
// grid=(64,6), 256 threads
// ---------------------------------------------------------------------------
__global__ void k_gram_part() {
    __shared__ float S[NN*133];
    int b = blockIdx.x, ch = blockIdx.y, tid = threadIdx.x;
    int tx = tid & 15, ty = tid >> 4;
    const float* Pm = g_proj + (size_t)b*NN*D_ + ch*128;
    float acc[5][5] = {};
    int i4 = (ty + 64 < NN) ? (ty + 64) : 0;
    int j4 = (tx + 64 < NN) ? (tx + 64) : 0;

    for (int idx = tid; idx < NN*128; idx += 256) {
        int i = idx >> 7, dd = idx & 127;
        S[i*133 + dd] = Pm[(size_t)i*D_ + dd];
    }
    __syncthreads();
    for (int dd = 0; dd < 128; dd++) {
        float av[5], bv[5];
        av[0]=S[(ty   )*133+dd]; av[1]=S[(ty+16)*133+dd];
        av[2]=S[(ty+32)*133+dd]; av[3]=S[(ty+48)*133+dd]; av[4]=S[i4*133+dd];
        bv[0]=S[(tx   )*133+dd]; bv[1]=S[(tx+16)*133+dd];
        bv[2]=S[(tx+32)*133+dd]; bv[3]=S[(tx+48)*133+dd]; bv[4]=S[j4*133+dd];
        #pragma unroll
        for (int u = 0; u < 5; u++)
            #pragma unroll
            for (int v = 0; v < 5; v++)
                acc[u][v] += av[u]*bv[v];
    }
    float* dst = g_gpart + ((size_t)ch*B_ + b)*SZ;
    #pragma unroll
    for (int u = 0; u < 5; u++) {
        int i = ty + 16*u; if (i >= NN) continue;
        #pragma unroll
        for (int v = 0; v < 5; v++) {
            int j = tx + 16*v; if (j >= NN) continue;
            dst[i*NN + j] = acc[u][v];
        }
    }
}

// ---------------------------------------------------------------------------
// Kernel D: gram-finalize + 8 Physarum steps.  512 threads (16 warps).
//   Solve: block elimination, PANEL=16 (4 big panels + one 1-panel):
//   barriers/step 29 -> 17, trailing smem traffic ~halved (one rank-16
//   update replaces two rank-8 passes). warp0 inverts the 16x16 pivot
//   block (lanes 0..15, Jordan, shfl); warps 1..15 stage sU; 16 warps
//   compute new pivot rows = Binv*sU; all warps apply trailing update
//   with live panel columns as multipliers. Diag becomes exactly 1 ->
//   p = aug column, no division pass.
//   Elementwise: ONE fused mega-pass per step (exact bitwise symmetry).
// grid=64, 512 threads.
// ---------------------------------------------------------------------------
__global__ void __launch_bounds__(ITPB, 1) k_iter(float* __restrict__ out) {
    __shared__ float sC[NN*LDA];
    __shared__ float sA[NN*LDA];
    __shared__ float sU[PBMAX*64];   // staged original pivot-row trailing
    __shared__ float sB[PBMAX*17];   // 16x16 panel-block inverse
    __shared__ float sp[NN];
    __shared__ float sInv[NN];
    __shared__ float sSsq[NN];
    __shared__ float sred[ITPB];
    int b = blockIdx.x, tid = threadIdx.x;
    int lane = tid & 31, w = tid >> 5;          // 16 warps
    float* dh = out + O_DH + (size_t)b*9*SZ;
    float* qh = out + O_QH + (size_t)b*8*SZ;

    // ---- norms from partial diagonals ----
    if (tid < NN) {
        float sq = 0.f;
        #pragma unroll
        for (int ch = 0; ch < 6; ch++)
            sq += g_gpart[((size_t)ch*B_ + b)*SZ + tid*66];   // diag
        float inv = 1.0f / fmaxf(sqrtf(sq), 1e-12f);
        sInv[tid] = inv;
        sSsq[tid] = sq * inv * inv;
    }
    __syncthreads();

    // ---- prologue: C0 (exact-symmetric), dh[0], system sA ----
    for (int i = w; i < NN; i += 16) {
        float ssqi = sSsq[i], invi = sInv[i];
        float deg = 0.f;
        #pragma unroll
        for (int seg = 0; seg < 3; seg++) {
            int j = lane + seg*32;
            if (j >= NN) continue;
            float s = 0.f;
            #pragma unroll
            for (int ch = 0; ch < 6; ch++)
                s += g_gpart[((size_t)ch*B_ + b)*SZ + i*65 + j];
            float dn = s * (invi * sInv[j]);            // commutative-exact
            float d2 = fmaxf(ssqi + sSsq[j] - 2.0f*dn, 0.0f);
            float v  = (i == j) ? 0.0f : fmaxf(__expf(-d2), FLOOR_);
            sC[i*LDA + j] = v;
            dh[i*65 + j]  = v;
            if (i != j) sA[i*LDA + j] = -v;
            deg += v;
        }
        #pragma unroll
        for (int o = 16; o > 0; o >>= 1) deg += __shfl_xor_sync(0xffffffffu, deg, o);
        if (lane == 0) {
            sA[i*LDA + i]  = deg + EPS_;
            sA[i*LDA + NN] = (i == 0) ? 1.0f : (-1.0f/64.0f);
        }
    }

    float st_acc = 0.f, sp_acc = 0.f;

    for (int step = 0; step < STEPS_; step++) {
        __syncthreads();
        // ======== block elimination via 16x16 panel inverse ========
        for (int k0 = 0; k0 < NN; k0 += PBMAX) {
            int PB = (NN - k0 < PBMAX) ? (NN - k0) : PBMAX;
            int T  = NN + 1 - (k0 + PB);       // trailing cols incl aug
            // ---- Phase A: warp0 inverts block; warps 1-15 stage sU ----
            if (w == 0) {
                float a[PBMAX];
                if (lane < PB) {
                    #pragma unroll
                    for (int u = 0; u < PBMAX; u++)
                        a[u] = (u < PB) ? sA[(k0+lane)*LDA + k0 + u] : 0.f;
                }
                #pragma unroll
                for (int t = 0; t < PBMAX; t++) {
                    if (t >= PB) break;
                    float prow[PBMAX];
                    #pragma unroll
                    for (int u = 0; u < PBMAX; u++)
                        prow[u] = __shfl_sync(0xffffffffu, a[u], t);
                    float pinv = __fdividef(1.0f, prow[t]);
                    if (lane < PB) {
                        if (lane == t) {
                            #pragma unroll
                            for (int u = 0; u < PBMAX; u++)
                                a[u] = (u == t) ? pinv : prow[u]*pinv;
                        } else {
                            float l = a[t];
                            float nl = -l*pinv;
                            a[t] = nl;
                            #pragma unroll
                            for (int u = 0; u < PBMAX; u++) if (u != t)
                                a[u] += nl * prow[u];
                        }
                    }
                }
                if (lane < PB) {
                    #pragma unroll
                    for (int u = 0; u < PBMAX; u++)
                        sB[lane*17 + u] = a[u];
                }
            } else {
                // stage original pivot-row trailing (incl aug) into sU
                for (int t = w - 1; t < PB; t += 15) {
                    #pragma unroll
                    for (int s = 0; s < 2; s++) {
                        int c = lane + 32*s;
                        if (c < T) sU[t*64 + c] = sA[(k0+t)*LDA + k0 + PB + c];
                    }
                }
            }
            __syncthreads();
            // ---- Phase B1: new pivot rows = Binv * sU (one row per warp) ----
            if (w < PB) {
                float bi[PBMAX];
                #pragma unroll
                for (int u = 0; u < PBMAX; u++)
                    bi[u] = (u < PB) ? sB[w*17 + u] : 0.f;
                #pragma unroll
                for (int s = 0; s < 2; s++) {
                    int c = lane + 32*s;
                    if (c < T) {
                        float x = 0.f;
                        #pragma unroll
                        for (int u = 0; u < PBMAX; u++)
                            x += bi[u] * sU[u*64 + c];
                        sA[(k0+w)*LDA + k0 + PB + c] = x;
                    }
                }
            }
            __syncthreads();
            // ---- Phase B2: trailing update, multipliers = live panel cols ----
            float Ur[PBMAX][2];
            #pragma unroll
            for (int t = 0; t < PBMAX; t++)
                #pragma unroll
                for (int s = 0; s < 2; s++) {
                    int c = lane + 32*s;
                    Ur[t][s] = (t < PB && c < T)
                             ? sA[(k0+t)*LDA + k0 + PB + c] : 0.f;
                }
            for (int i = w; i < NN; i += 16) {
                if (i >= k0 && i < k0 + PB) continue;
                float ap[PBMAX];
                #pragma unroll
                for (int u = 0; u < PBMAX; u++)
                    ap[u] = (u < PB) ? sA[i*LDA + k0 + u] : 0.f;   // broadcast
                #pragma unroll
                for (int s = 0; s < 2; s++) {
                    int c = lane + 32*s;
                    if (c < T) {
                        int j = k0 + PB + c;
                        float x = sA[i*LDA + j];
                        #pragma unroll
                        for (int t = 0; t < PBMAX; t++) x -= ap[t] * Ur[t][s];
                        sA[i*LDA + j] = x;
                    }
                }
            }
            __syncthreads();
        }
        // diag is exactly 1 for all rows -> p = aug column directly
        if (tid < NN) sp[tid] = sA[tid*LDA + NN];
        __syncthreads();
        // ======== fused mega-pass ========
        bool last = (step == STEPS_-1);
        float* qhs = qh + (size_t)step*SZ;
        float* dhs = dh + (size_t)(step+1)*SZ;
        for (int i = w; i < NN; i += 16) {
            float pi = sp[i];
            float deg = 0.f, gfl = 0.f;
            #pragma unroll
            for (int seg = 0; seg < 3; seg++) {
                int j = lane + seg*32;
                if (j >= NN) continue;
                float c  = sC[i*LDA + j];
                float fl = c * (pi - sp[j]);
                qhs[i*65 + j] = fl;
                float r = fabsf(fl);            // MU = 1
                r = __fdividef(r, 1.0f + r);
                float nv = (i == j) ? 0.f
                         : fmaxf(c + DT_*(r - GAMMA_*c), FLOOR_);
                sC[i*LDA + j] = nv;
                dhs[i*65 + j] = nv;
                if (i != j) sA[i*LDA + j] = -nv;
                st_acc += fabsf(nv - c);
                deg += nv;
                if (last) {
                    gfl += fabsf(fl);
                    if (i >= 1 && j >= 1) sp_acc += nv;
                }
            }
            #pragma unroll
            for (int o = 16; o > 0; o >>= 1) {
                deg += __shfl_xor_sync(0xffffffffu, deg, o);
                if (last) gfl += __shfl_xor_sync(0xffffffffu, gfl, o);
            }
            if (lane == 0) {
                sA[i*LDA + i]  = deg + EPS_;
                sA[i*LDA + NN] = (i == 0) ? 1.0f : (-1.0f/64.0f);
                if (last && i >= 1) g_gf[b*G_ + i - 1] = gfl;
            }
        }
    }
    __syncthreads();
    // ---- aux reductions (fixed-order, deterministic) ----
    sred[tid] = sp_acc; __syncthreads();
    for (int s = ITPB/2; s > 0; s >>= 1) { if (tid < s) sred[tid] += sred[tid+s]; __syncthreads(); }
    if (tid == 0) g_aux[2*b] = sred[0];
    __syncthreads();
    sred[tid] = st_acc; __syncthreads();
    for (int s = ITPB/2; s > 0; s >>= 1) { if (tid < s) sred[tid] += sred[tid+s]; __syncthreads(); }
    if (tid == 0) g_aux[2*b + 1] = sred[0];
}

// ---------------------------------------------------------------------------
// Kernel E: scores, exact stable top-288, masks, gid, routing.
// grid=64, 576 threads
// ---------------------------------------------------------------------------
__device__ __forceinline__ float redsum576(float v, float* sred) {
    int tid = threadIdx.x;
    sred[tid] = v; __syncthreads();
    if (tid < 64) sred[tid] += sred[tid + 512];
    __syncthreads();
    for (int s = 256; s > 0; s >>= 1) {
        if (tid < s) sred[tid] += sred[tid + s];
        __syncthreads();
    }
    float r = sred[0];
    __syncthreads();
    return r;
}

__global__ void k_score(const float* __restrict__ local,
                        float* __restrict__ out) {
    __shared__ float sred[576];
    __shared__ float sts[576];
    __shared__ float sgs[64];
    __shared__ float srow[64];
    int b = blockIdx.x, tid = threadIdx.x;

    float lv  = local[(size_t)b*P_ + tid];
    float lm  = redsum576(lv, sred) / 576.0f;
    float lc  = lv - lm;
    float lvr = redsum576(lc*lc, sred) / 575.0f;
    float lsn = lc / fmaxf(sqrtf(lvr), 1e-6f);

    float gv  = (tid < 64) ? g_gf[b*G_ + tid] : 0.f;
    float gm  = redsum576(gv, sred) / 64.0f;
    float gc  = gv - gm;
    float gvr = redsum576((tid < 64) ? gc*gc : 0.f, sred) / 63.0f;
    if (tid < 64) sgs[tid] = gc / fmaxf(sqrtf(gvr), 1e-6f);
    __syncthreads();

    int row = tid / 24, col = tid % 24;
    int g   = (row/3)*8 + (col/3);
    float gs = sgs[g];
    float ts = 1.0f*gs + 0.5f*lsn;
    sts[tid] = ts;
    out[O_GID + (size_t)b*P_ + tid] = (float)g;
    out[O_GS  + (size_t)b*P_ + tid] = gs;
    __syncthreads();

    int cnt = 0;
    for (int q = 0; q < P_; q++) {
        float v = sts[q];
        cnt += (v > ts) || (v == ts && q < tid);
    }
    float keep = (cnt < 288) ? 1.0f : 0.0f;
    out[O_PATCH + (size_t)b*P_ + tid]      = keep;
    out[O_KEEP  + (size_t)b*577 + 1 + tid] = keep;

    const float* dh8 = out + O_DH + ((size_t)b*9 + 8)*SZ;
    if (tid < 64) {
        float s = 0.f;
        for (int j = 0; j < 64; j++) s += dh8[(tid+1)*NN + (j+1)];
        srow[tid] = fmaxf(s, 1e-6f);
    }
    __syncthreads();
    for (int idx = tid; idx < 4096; idx += 576) {
        int i = idx >> 6, j = idx & 63;
        out[O_RT + (size_t)b*4096 + idx] = dh8[(i+1)*NN + (j+1)] / srow[i];
    }
}

// ---------------------------------------------------------------------------
// Kernel F: aux scalars (fixed-order tree, deterministic). 64 threads
// ---------------------------------------------------------------------------
__global__ void k_aux(float* __restrict__ out) {
    __shared__ float s1[64], s2[64];
    int tid = threadIdx.x;
    s1[tid] = g_aux[2*tid];
    s2[tid] = g_aux[2*tid + 1];
    __syncthreads();
    for (int s = 32; s > 0; s >>= 1) {
        if (tid < s) { s1[tid] += s1[tid+s]; s2[tid] += s2[tid+s]; }
        __syncthreads();
    }
    if (tid == 0) {
        out[O_AUX]     = s1[0] / 64.0f;   // aux_sparse
        out[O_AUX + 1] = s2[0] / 64.0f;   // aux_stable
    }
}

// ---------------------------------------------------------------------------
extern "C" void kernel_launch(void* const* d_in, const int* in_sizes, int n_in,
                              void* d_out, int out_size) {
    const float* tokens = (const float*)d_in[0];
    const float* cls    = (const float*)d_in[1];
    const float* Wm     = (const float*)d_in[2];
    const float* local  = (const float*)d_in[3];
    float* out = (float*)d_out;

    k_group    <<<dim3(65, 64), 192>>>(tokens, cls, out);  // launch 0
    k_gemm     <<<dim3(66, 6), 128>>>(Wm);                 // launch 1
    k_gram_part<<<dim3(64, 6), 256>>>();                   // launch 2
    k_iter     <<<64, ITPB>>>(out);                        // launch 3 <- probe
    k_score    <<<64, 576>>>(local, out);                  // launch 4
    k_aux      <<<1, 64>>>(out);                           // launch 5
}

// round 16
// speedup vs baseline: 1.1318x; 1.1318x over previous
#include <cuda_runtime.h>
#include <cstdint>

#define B_      64
#define P_      576
#define D_      768
#define G_      64
#define NN      65
#define SZ      4225      // 65*65
#define LDA     68        // even: float2-aligned rows; cols 66,67 = padding
#define STEPS_  8
#define FLOOR_  0.0001f
#define EPS_    0.0001f
#define DT_     0.1f
#define GAMMA_  0.1f

#define MPAD    4224      // 66*64, padded row count for GEMM tiles
#define ITPB    768       // k_iter threads per block (24 warps)
#define NW      24        // k_iter warps

// Output layout offsets (flattened tuple, float32)
#define O_KEEP   0          // (64,577)
#define O_PATCH  36928      // (64,576)
#define O_GID    73792      // (64,576)
#define O_GS     110656     // (64,576)
#define O_DH     147520     // (64,9,65,65)
#define O_QH     2581120    // (64,8,65,65)
#define O_RT     4744320    // (64,64,64)
#define O_AUX    5006464    // 2 scalars

// Scratch (static device globals — zero-initialized at load, never alloc'd)
__device__ float g_nodes[MPAD*D_];      // padded rows 4160..4223 stay zero
__device__ float g_proj [MPAD*D_];
__device__ float g_gf   [B_*G_];
__device__ float g_aux  [B_*2];
__device__ float g_gpart[6*B_*SZ];      // split-K gram partials (raw dot products)

// Packed dual-fp32 FMA (FFMA2) — exact fp32, 2x FFMA throughput
#define FMA2(c, a, b) asm("fma.rn.f32x2 %0, %1, %2, %0;" : "+l"(c) : "l"(a), "l"(b))
// Duplicate one fp32 into both halves of a b64 (register-side, ALU pipe)
#define PACK2(d, s)   asm("mov.b64 %0, {%1, %1};" : "=l"(d) : "f"(s))
// Pack two fp32 into a b64
#define PACKAB(d, x, y) asm("mov.b64 %0, {%1, %2};" : "=l"(d) : "f"(x), "f"(y))

// ---------------------------------------------------------------------------
// Kernel A: group means + cls + keep-col init.  grid=(65,64), 192 threads
// ---------------------------------------------------------------------------
__global__ void k_group(const float* __restrict__ tokens,
                        const float* __restrict__ cls,
                        float* __restrict__ out) {
    int n = blockIdx.x;      // node 0..64
    int b = blockIdx.y;
    int tid = threadIdx.x;   // 0..191, one float4 each
    float4* dst = (float4*)(g_nodes + ((size_t)b*NN + n)*D_);
    if (n == 0) {
        dst[tid] = ((const float4*)(cls + (size_t)b*D_))[tid];
        if (tid == 0) out[O_KEEP + (size_t)b*577] = 1.0f;
    } else {
        int g  = n - 1;
        int r0 = (g >> 3) * 3, c0 = (g & 7) * 3;
        const float4* base = (const float4*)(tokens + (size_t)b*P_*D_);
        float4 s = make_float4(0.f, 0.f, 0.f, 0.f);
        #pragma unroll
        for (int dr = 0; dr < 3; dr++)
            #pragma unroll
            for (int dc = 0; dc < 3; dc++) {
                float4 v = base[(size_t)((r0+dr)*24 + (c0+dc))*(D_/4) + tid];
                s.x += v.x; s.y += v.y; s.z += v.z; s.w += v.w;
            }
        const float inv9 = 1.0f/9.0f;
        s.x *= inv9; s.y *= inv9; s.z *= inv9; s.w *= inv9;
        dst[tid] = s;
    }
}

// ---------------------------------------------------------------------------
// Kernel B: GEMM  proj[r,e] = sum_d nodes[r,d] * W[e,d]   (FFMA2, R4 version)
//   Tile 64x128x16, 128 threads, 16x4 microtile.  grid=(66,6)
// ---------------------------------------------------------------------------
__global__ void __launch_bounds__(128, 3) k_gemm(const float* __restrict__ Wm) {
    __shared__ float As[64][20];     // [m][k], pad 20
    __shared__ float Bs[16][132];    // [k][n], pad 132
    int tid  = threadIdx.x;
    int lane = tid & 31, w = tid >> 5;         // 4 warps
    int m0 = blockIdx.x * 64, n0 = blockIdx.y * 128;

    unsigned long long acc[16][2] = {};        // 16 m-rows x (2 f32x2 = 4 n)

    for (int k0 = 0; k0 < D_; k0 += 16) {
        #pragma unroll
        for (int h = 0; h < 2; h++) {
            int idx = tid + h*128;
            int row = idx >> 2, c4 = (idx & 3) << 2;
            float4 v = *(const float4*)(g_nodes + (size_t)(m0+row)*D_ + k0 + c4);
            *(float4*)&As[row][c4] = v;
        }
        #pragma unroll
        for (int h = 0; h < 4; h++) {
            int idx = tid + h*128;
            int row = idx >> 2, c4 = (idx & 3) << 2;
            float4 v = *(const float4*)(Wm + (size_t)(n0+row)*D_ + k0 + c4);
            Bs[c4+0][row] = v.x; Bs[c4+1][row] = v.y;
            Bs[c4+2][row] = v.z; Bs[c4+3][row] = v.w;
        }
        __syncthreads();
        #pragma unroll
        for (int kk2 = 0; kk2 < 8; kk2++) {
            float2 av[16];
            #pragma unroll
            for (int r = 0; r < 16; r++)
                av[r] = *(const float2*)&As[w*16 + r][kk2*2];   // broadcast
            #pragma unroll
            for (int e = 0; e < 2; e++) {
                int kk = kk2*2 + e;
                ulonglong2 bb = *(const ulonglong2*)&Bs[kk][lane*4];
                #pragma unroll
                for (int r = 0; r < 16; r++) {
                    unsigned long long a2;
                    PACK2(a2, e ? av[r].y : av[r].x);
                    FMA2(acc[r][0], a2, bb.x);
                    FMA2(acc[r][1], a2, bb.y);
                }
            }
        }
        __syncthreads();
    }
    #pragma unroll
    for (int r = 0; r < 16; r++) {
        float4 o;
        o.x = __uint_as_float((unsigned)(acc[r][0]));
        o.y = __uint_as_float((unsigned)(acc[r][0] >> 32));
        o.z = __uint_as_float((unsigned)(acc[r][1]));
        o.w = __uint_as_float((unsigned)(acc[r][1] >> 32));
        *(float4*)(g_proj + (size_t)(m0 + w*16 + r)*D_ + n0 + lane*4) = o;
    }
}

// ---------------------------------------------------------------------------
// Kernel C: per-batch Gram partials on RAW proj, split-K 6 x 128.
// grid=(64,6), 256 threads
// ---------------------------------------------------------------------------
__global__ void k_gram_part() {
    __shared__ float S[NN*133];
    int b = blockIdx.x, ch = blockIdx.y, tid = threadIdx.x;
    int tx = tid & 15, ty = tid >> 4;
    const float* Pm = g_proj + (size_t)b*NN*D_ + ch*128;
    float acc[5][5] = {};
    int i4 = (ty + 64 < NN) ? (ty + 64) : 0;
    int j4 = (tx + 64 < NN) ? (tx + 64) : 0;

    for (int idx = tid; idx < NN*128; idx += 256) {
        int i = idx >> 7, dd = idx & 127;
        S[i*133 + dd] = Pm[(size_t)i*D_ + dd];
    }
    __syncthreads();
    for (int dd = 0; dd < 128; dd++) {
        float av[5], bv[5];
        av[0]=S[(ty   )*133+dd]; av[1]=S[(ty+16)*133+dd];
        av[2]=S[(ty+32)*133+dd]; av[3]=S[(ty+48)*133+dd]; av[4]=S[i4*133+dd];
        bv[0]=S[(tx   )*133+dd]; bv[1]=S[(tx+16)*133+dd];
        bv[2]=S[(tx+32)*133+dd]; bv[3]=S[(tx+48)*133+dd]; bv[4]=S[j4*133+dd];
        #pragma unroll
        for (int u = 0; u < 5; u++)
            #pragma unroll
            for (int v = 0; v < 5; v++)
                acc[u][v] += av[u]*bv[v];
    }
    float* dst = g_gpart + ((size_t)ch*B_ + b)*SZ;
    #pragma unroll
    for (int u = 0; u < 5; u++) {
        int i = ty + 16*u; if (i >= NN) continue;
        #pragma unroll
        for (int v = 0; v < 5; v++) {
            int j = tx + 16*v; if (j >= NN) continue;
            dst[i*NN + j] = acc[u][v];
        }
    }
}

// ---------------------------------------------------------------------------
// Kernel D: gram-finalize + 8 Physarum steps.  768 threads (24 warps).
//   Solve: block elimination, 8 uniform PB=8 panels (pivots 0..63) + a
//   closed-form 2-barrier epilogue for pivot 64 (no degenerate 9th panel).
//   LDA=68 (even): staging/B1/B2 fully float2-vectorized, B2 update via
//   FMA2 with pre-negated Ur (exact fp32). Phase A = warp0 8x8 Jordan
//   inverse in registers (unchanged, known-good).
//   Elementwise: ONE fused mega-pass per step (exact bitwise symmetry).
// grid=64, 768 threads.
// ---------------------------------------------------------------------------
__global__ void __launch_bounds__(ITPB, 1) k_iter(float* __restrict__ out) {
    __shared__ __align__(16) float sC[NN*LDA];
    __shared__ __align__(16) float sA[NN*LDA];
    __shared__ __align__(16) float sU[8*64];   // staged original pivot-row trailing
    __shared__ __align__(16) float sB[8*9];    // 8x8 panel-block inverse
    __shared__ __align__(16) float sp[NN+1];
    __shared__ float sInv[NN];
    __shared__ float sSsq[NN];
    __shared__ float sred[ITPB];
    int b = blockIdx.x, tid = threadIdx.x;
    int lane = tid & 31, w = tid >> 5;          // 24 warps
    int cc = 2*lane;                            // column-pair offset
    float* dh = out + O_DH + (size_t)b*9*SZ;
    float* qh = out + O_QH + (size_t)b*8*SZ;

    // ---- norms from partial diagonals ----
    if (tid < NN) {
        float sq = 0.f;
        #pragma unroll
        for (int ch = 0; ch < 6; ch++)
            sq += g_gpart[((size_t)ch*B_ + b)*SZ + tid*66];   // diag
        float inv = 1.0f / fmaxf(sqrtf(sq), 1e-12f);
        sInv[tid] = inv;
        sSsq[tid] = sq * inv * inv;
    }
    __syncthreads();

    // ---- prologue: C0 (exact-symmetric), dh[0], system sA ----
    for (int i = w; i < NN; i += NW) {
        float ssqi = sSsq[i], invi = sInv[i];
        float deg = 0.f;
        #pragma unroll
        for (int seg = 0; seg < 3; seg++) {
            int j = lane + seg*32;
            if (j >= NN) continue;
            float s = 0.f;
            #pragma unroll
            for (int ch = 0; ch < 6; ch++)
                s += g_gpart[((size_t)ch*B_ + b)*SZ + i*65 + j];
            float dn = s * (invi * sInv[j]);            // commutative-exact
            float d2 = fmaxf(ssqi + sSsq[j] - 2.0f*dn, 0.0f);
            float v  = (i == j) ? 0.0f : fmaxf(__expf(-d2), FLOOR_);
            sC[i*LDA + j] = v;
            dh[i*65 + j]  = v;
            if (i != j) sA[i*LDA + j] = -v;
            deg += v;
        }
        #pragma unroll
        for (int o = 16; o > 0; o >>= 1) deg += __shfl_xor_sync(0xffffffffu, deg, o);
        if (lane == 0) {
            sA[i*LDA + i]  = deg + EPS_;
            sA[i*LDA + NN] = (i == 0) ? 1.0f : (-1.0f/64.0f);
        }
    }

    float st_acc = 0.f, sp_acc = 0.f;

    for (int step = 0; step < STEPS_; step++) {
        __syncthreads();
        // ======== 8 uniform PB=8 panels (pivots 0..63) ========
        for (int k0 = 0; k0 < 64; k0 += 8) {
            int T = NN + 1 - (k0 + 8);          // trailing cols incl aug; even
            // ---- Phase A: warp0 inverts 8x8 block; warps 1..8 stage sU ----
            if (w == 0) {
                float a[8];
                if (lane < 8) {
                    #pragma unroll
                    for (int u = 0; u < 8; u++)
                        a[u] = sA[(k0+lane)*LDA + k0 + u];
                }
                #pragma unroll
                for (int t = 0; t < 8; t++) {
                    float prow[8];
                    #pragma unroll
                    for (int u = 0; u < 8; u++)
                        prow[u] = __shfl_sync(0xffffffffu, a[u], t);
                    float pinv = __fdividef(1.0f, prow[t]);
                    if (lane < 8) {
                        if (lane == t) {
                            #pragma unroll
                            for (int u = 0; u < 8; u++)
                                a[u] = (u == t) ? pinv : prow[u]*pinv;
                        } else {
                            float nl = -a[t]*pinv;
                            a[t] = nl;
                            #pragma unroll
                            for (int u = 0; u < 8; u++) if (u != t)
                                a[u] += nl * prow[u];
                        }
                    }
                }
                if (lane < 8) {
                    #pragma unroll
                    for (int u = 0; u < 8; u++)
                        sB[lane*9 + u] = a[u];
                }
            } else {
                // stage original pivot-row trailing (incl aug), float2
                for (int t = w - 1; t < 8; t += (NW-1)) {
                    if (cc < T)
                        *(float2*)&sU[t*64 + cc] =
                            *(const float2*)&sA[(k0+t)*LDA + k0 + 8 + cc];
                }
            }
            __syncthreads();
            // ---- Phase B1: new pivot rows = Binv * sU (FMA2) ----
            if (w < 8) {
                unsigned long long bi2[8];
                #pragma unroll
                for (int u = 0; u < 8; u++) {
                    float bv = sB[w*9 + u];
                    PACK2(bi2[u], bv);
                }
                if (cc < T) {
                    unsigned long long x2 = 0ull;   // (0.0f, 0.0f)
                    #pragma unroll
                    for (int u = 0; u < 8; u++) {
                        unsigned long long s2 =
                            *(const unsigned long long*)&sU[u*64 + cc];
                        FMA2(x2, bi2[u], s2);
                    }
                    *(unsigned long long*)&sA[(k0+w)*LDA + k0 + 8 + cc] = x2;
                }
            }
            __syncthreads();
            // ---- Phase B2: trailing rank-8 update (FMA2, Ur pre-negated) ----
            unsigned long long UrN[8];
            #pragma unroll
            for (int t = 0; t < 8; t++) {
                float u0 = 0.f, u1 = 0.f;
                if (cc < T) {
                    float2 v = *(const float2*)&sA[(k0+t)*LDA + k0 + 8 + cc];
                    u0 = -v.x; u1 = -v.y;
                }
                PACKAB(UrN[t], u0, u1);
            }
            for (int i = w; i < NN; i += NW) {
                if (i >= k0 && i < k0 + 8) continue;
                unsigned long long ap2[8];
                #pragma unroll
                for (int u4 = 0; u4 < 4; u4++) {
                    float2 v = *(const float2*)&sA[i*LDA + k0 + 2*u4];
                    PACK2(ap2[2*u4],   v.x);
                    PACK2(ap2[2*u4+1], v.y);
                }
                if (cc < T) {
                    unsigned long long x2 =
                        *(const unsigned long long*)&sA[i*LDA + k0 + 8 + cc];
                    #pragma unroll
                    for (int t = 0; t < 8; t++)
                        FMA2(x2, ap2[t], UrN[t]);
                    *(unsigned long long*)&sA[i*LDA + k0 + 8 + cc] = x2;
                }
            }
            __syncthreads();
        }
        // ======== closed-form pivot-64 epilogue ========
        if (tid == 0)
            sp[64] = __fdividef(sA[64*LDA + 65], sA[64*LDA + 64]);
        __syncthreads();
        if (tid < 64)
            sp[tid] = sA[tid*LDA + 65] - sA[tid*LDA + 64]*sp[64];
        __syncthreads();
        // ======== fused mega-pass ========
        bool last = (step == STEPS_-1);
        float* qhs = qh + (size_t)step*SZ;
        float* dhs = dh + (size_t)(step+1)*SZ;
        for (int i = w; i < NN; i += NW) {
            float pi = sp[i];
            float deg = 0.f, gfl = 0.f;
            #pragma unroll
            for (int seg = 0; seg < 3; seg++) {
                int j = lane + seg*32;
                if (j >= NN) continue;
                float c  = sC[i*LDA + j];
                float fl = c * (pi - sp[j]);
                qhs[i*65 + j] = fl;
                float r = fabsf(fl);            // MU = 1
                r = __fdividef(r, 1.0f + r);
                float nv = (i == j) ? 0.f
                         : fmaxf(c + DT_*(r - GAMMA_*c), FLOOR_);
                sC[i*LDA + j] = nv;
                dhs[i*65 + j] = nv;
                if (i != j) sA[i*LDA + j] = -nv;
                st_acc += fabsf(nv - c);
                deg += nv;
                if (last) {
                    gfl += fabsf(fl);
                    if (i >= 1 && j >= 1) sp_acc += nv;
                }
            }
            #pragma unroll
            for (int o = 16; o > 0; o >>= 1) {
                deg += __shfl_xor_sync(0xffffffffu, deg, o);
                if (last) gfl += __shfl_xor_sync(0xffffffffu, gfl, o);
            }
            if (lane == 0) {
                sA[i*LDA + i]  = deg + EPS_;
                sA[i*LDA + NN] = (i == 0) ? 1.0f : (-1.0f/64.0f);
                if (last && i >= 1) g_gf[b*G_ + i - 1] = gfl;
            }
        }
    }
    __syncthreads();
    // ---- aux reductions (fixed-order, deterministic; 768 = 3*256 fold) ----
    sred[tid] = sp_acc; __syncthreads();
    if (tid < 256) sred[tid] += sred[tid+256] + sred[tid+512];
    __syncthreads();
    for (int s = 128; s > 0; s >>= 1) { if (tid < s) sred[tid] += sred[tid+s]; __syncthreads(); }
    if (tid == 0) g_aux[2*b] = sred[0];
    __syncthreads();
    sred[tid] = st_acc; __syncthreads();
    if (tid < 256) sred[tid] += sred[tid+256] + sred[tid+512];
    __syncthreads();
    for (int s = 128; s > 0; s >>= 1) { if (tid < s) sred[tid] += sred[tid+s]; __syncthreads(); }
    if (tid == 0) g_aux[2*b + 1] = sred[0];
}

// ---------------------------------------------------------------------------
// Kernel E: scores, exact stable top-288, masks, gid, routing.
// grid=64, 576 threads
// ---------------------------------------------------------------------------
__device__ __forceinline__ float redsum576(float v, float* sred) {
    int tid = threadIdx.x;
    sred[tid] = v; __syncthreads();
    if (tid < 64) sred[tid] += sred[tid + 512];
    __syncthreads();
    for (int s = 256; s > 0; s >>= 1) {
        if (tid < s) sred[tid] += sred[tid + s];
        __syncthreads();
    }
    float r = sred[0];
    __syncthreads();
    return r;
}

__global__ void k_score(const float* __restrict__ local,
                        float* __restrict__ out) {
    __shared__ float sred[576];
    __shared__ float sts[576];
    __shared__ float sgs[64];
    __shared__ float srow[64];
    int b = blockIdx.x, tid = threadIdx.x;

    float lv  = local[(size_t)b*P_ + tid];
    float lm  = redsum576(lv, sred) / 576.0f;
    float lc  = lv - lm;
    float lvr = redsum576(lc*lc, sred) / 575.0f;
    float lsn = lc / fmaxf(sqrtf(lvr), 1e-6f);

    float gv  = (tid < 64) ? g_gf[b*G_ + tid] : 0.f;
    float gm  = redsum576(gv, sred) / 64.0f;
    float gc  = gv - gm;
    float gvr = redsum576((tid < 64) ? gc*gc : 0.f, sred) / 63.0f;
    if (tid < 64) sgs[tid] = gc / fmaxf(sqrtf(gvr), 1e-6f);
    __syncthreads();

    int row = tid / 24, col = tid % 24;
    int g   = (row/3)*8 + (col/3);
    float gs = sgs[g];
    float ts = 1.0f*gs + 0.5f*lsn;
    sts[tid] = ts;
    out[O_GID + (size_t)b*P_ + tid] = (float)g;
    out[O_GS  + (size_t)b*P_ + tid] = gs;
    __syncthreads();

    int cnt = 0;
    for (int q = 0; q < P_; q++) {
        float v = sts[q];
        cnt += (v > ts) || (v == ts && q < tid);
    }
    float keep = (cnt < 288) ? 1.0f : 0.0f;
    out[O_PATCH + (size_t)b*P_ + tid]      = keep;
    out[O_KEEP  + (size_t)b*577 + 1 + tid] = keep;

    const float* dh8 = out + O_DH + ((size_t)b*9 + 8)*SZ;
    if (tid < 64) {
        float s = 0.f;
        for (int j = 0; j < 64; j++) s += dh8[(tid+1)*NN + (j+1)];
        srow[tid] = fmaxf(s, 1e-6f);
    }
    __syncthreads();
    for (int idx = tid; idx < 4096; idx += 576) {
        int i = idx >> 6, j = idx & 63;
        out[O_RT + (size_t)b*4096 + idx] = dh8[(i+1)*NN + (j+1)] / srow[i];
    }
}

// ---------------------------------------------------------------------------
// Kernel F: aux scalars (fixed-order tree, deterministic). 64 threads
// ---------------------------------------------------------------------------
__global__ void k_aux(float* __restrict__ out) {
    __shared__ float s1[64], s2[64];
    int tid = threadIdx.x;
    s1[tid] = g_aux[2*tid];
    s2[tid] = g_aux[2*tid + 1];
    __syncthreads();
    for (int s = 32; s > 0; s >>= 1) {
        if (tid < s) { s1[tid] += s1[tid+s]; s2[tid] += s2[tid+s]; }
        __syncthreads();
    }
    if (tid == 0) {
        out[O_AUX]     = s1[0] / 64.0f;   // aux_sparse
        out[O_AUX + 1] = s2[0] / 64.0f;   // aux_stable
    }
}

// ---------------------------------------------------------------------------
extern "C" void kernel_launch(void* const* d_in, const int* in_sizes, int n_in,
                              void* d_out, int out_size) {
    const float* tokens = (const float*)d_in[0];
    const float* cls    = (const float*)d_in[1];
    const float* Wm     = (const float*)d_in[2];
    const float* local  = (const float*)d_in[3];
    float* out = (float*)d_out;

    k_group    <<<dim3(65, 64), 192>>>(tokens, cls, out);  // launch 0
    k_gemm     <<<dim3(66, 6), 128>>>(Wm);                 // launch 1
    k_gram_part<<<dim3(64, 6), 256>>>();                   // launch 2
    k_iter     <<<64, ITPB>>>(out);                        // launch 3 <- probe
    k_score    <<<64, 576>>>(local, out);                  // launch 4
    k_aux      <<<1, 64>>>(out);                           // launch 5
}